// round 1
// baseline (speedup 1.0000x reference)
#include <cuda_runtime.h>
#include <math.h>

// ---------------------------------------------------------------------------
// Problem constants: B=512, T=256, F=64, N=128
//   e1: BiLSTM  in=64   u=128   -> h1 [B,T,256]
//   e2: 2xLSTM  in=256  u=64    -> final states z [B,128]
//   d1: BiLSTM  in=128(const z) u=64  -> hd1 [B,T,128]
//   d2: BiLSTM  in=128  u=128   -> hd2 [B,T,256]
//   dense: 256 -> 64
// Gates: split z4 into (i,f,g,o); i,f,o sigmoid; g relu; c=f*c+i*g; h=o*relu(c)
// ---------------------------------------------------------------------------

#define BT 131072  // B*T

// Scratch (device globals; no allocation allowed)
__device__ float g_xz1[134217728];   // [BT,1024] e1 xz (both dirs), reused for d2 xz
__device__ float g_xz2[67108864];    // [BT, 512] e2 xz
__device__ float g_h1 [33554432];    // [BT, 256] e1 output, reused for d2 output
__device__ float g_hd1[16777216];    // [BT, 128] d1 output
__device__ float g_z  [65536];       // [B, 128]  e2 final states
__device__ float g_xzd1[262144];     // [B, 512]  d1 xz (constant over t)

__device__ __forceinline__ float sigm(float x) {
    return __fdividef(1.0f, 1.0f + __expf(-x));
}

// ---------------------------------------------------------------------------
// SGEMM with bias: C[M,N] = A[M,K] @ W[K,N] + bias[N]
// A row-major ld=K, W row-major ld=N, C row stride = ldc.
// 128x128 tile, BK=8, 256 threads, 8x8 per thread.
// M must be a multiple of 128, K a multiple of 8. N guarded.
// ---------------------------------------------------------------------------
__global__ __launch_bounds__(256) void sgemm_bias(
    const float* __restrict__ A, const float* __restrict__ W,
    const float* __restrict__ bias, float* __restrict__ C,
    int M, int N, int K, int ldc)
{
    __shared__ float As[8][128];
    __shared__ float Bs[8][128];

    const int tid = threadIdx.x;
    const int bm = blockIdx.y * 128;
    const int bn = blockIdx.x * 128;
    const int m0 = (tid / 16) * 8;
    const int n0 = (tid % 16) * 8;

    const int arow = tid / 2, acol = (tid % 2) * 4;
    const int brow = tid / 32, bcol = (tid % 32) * 4;

    float acc[8][8];
    #pragma unroll
    for (int i = 0; i < 8; i++)
        #pragma unroll
        for (int j = 0; j < 8; j++) acc[i][j] = 0.0f;

    for (int k0 = 0; k0 < K; k0 += 8) {
        float4 a4 = *(const float4*)(A + (size_t)(bm + arow) * K + k0 + acol);
        As[acol + 0][arow] = a4.x;
        As[acol + 1][arow] = a4.y;
        As[acol + 2][arow] = a4.z;
        As[acol + 3][arow] = a4.w;

        float4 b4 = make_float4(0.f, 0.f, 0.f, 0.f);
        if (bn + bcol < N)
            b4 = *(const float4*)(W + (size_t)(k0 + brow) * N + bn + bcol);
        *(float4*)&Bs[brow][bcol] = b4;

        __syncthreads();

        #pragma unroll
        for (int kk = 0; kk < 8; kk++) {
            float a[8], b[8];
            *(float4*)(a)     = *(const float4*)&As[kk][m0];
            *(float4*)(a + 4) = *(const float4*)&As[kk][m0 + 4];
            *(float4*)(b)     = *(const float4*)&Bs[kk][n0];
            *(float4*)(b + 4) = *(const float4*)&Bs[kk][n0 + 4];
            #pragma unroll
            for (int i = 0; i < 8; i++)
                #pragma unroll
                for (int j = 0; j < 8; j++)
                    acc[i][j] += a[i] * b[j];
        }
        __syncthreads();
    }

    #pragma unroll
    for (int i = 0; i < 8; i++) {
        size_t row = (size_t)(bm + m0 + i) * ldc;
        #pragma unroll
        for (int j = 0; j < 8; j++) {
            int n = bn + n0 + j;
            if (n < N) C[row + n] = acc[i][j] + bias[n];
        }
    }
}

// ---------------------------------------------------------------------------
// LSTM recurrence for one layer. Grid: (64 batch chunks, 2 directions).
// Block: 256 threads, Bc=8 batch rows per block.
// Per step: z4 = xz[t] + h @ U ; gate math ; h,c update.
// U is gate-interleaved float4 per (k,j): KSMEM rows in smem, rest in registers
// (all of U on-chip -> no per-step L2 weight traffic).
// h double-buffered in smem (transposed [k][b] for vector loads).
// xz addressing: xz + dir*4*HU + b*strideB + t*strideT + gate*HU + j
// Output: out + dir*HU + (SEQ ? (b*T+tt)*ldo : b*ldo) + j
// ---------------------------------------------------------------------------
template<int HU, int KSMEM, bool SEQ>
__global__ __launch_bounds__(256, 1)
void lstm_kernel(const float* __restrict__ xz, size_t strideB, size_t strideT,
                 const float* __restrict__ Uf, const float* __restrict__ Ub,
                 float* __restrict__ out, int ldo, int T)
{
    constexpr int NB   = HU / 32;        // batch rows per thread (4 for HU=128, 2 for HU=64)
    constexpr int REGK = HU - KSMEM;     // U rows held in registers

    extern __shared__ float4 sm4[];
    float4* Us4 = sm4;                          // [KSMEM*HU] gate-interleaved U
    float*  hS  = (float*)(sm4 + KSMEM * HU);   // [2][HU][8] h state (double buffered)

    const int tid = threadIdx.x;
    const int j   = tid % HU;
    const int bg  = tid / HU;
    const int dir = blockIdx.y;
    const int b0  = blockIdx.x * 8 + bg * NB;

    const float* U    = dir ? Ub : Uf;
    const float* xzd  = xz + (size_t)dir * (4 * HU);
    float*       outd = out + dir * HU;

    // Load U (smem portion), gate-interleaved.
    for (int idx = tid; idx < KSMEM * HU; idx += 256) {
        int k = idx / HU, jj = idx % HU;
        const float* ur = U + (size_t)k * (4 * HU) + jj;
        Us4[idx] = make_float4(ur[0], ur[HU], ur[2 * HU], ur[3 * HU]);
    }
    // Load U (register portion) for this thread's column j.
    float4 wreg[REGK > 0 ? REGK : 1];
    #pragma unroll
    for (int r = 0; r < REGK; r++) {
        const float* ur = U + (size_t)(KSMEM + r) * (4 * HU) + j;
        wreg[r] = make_float4(ur[0], ur[HU], ur[2 * HU], ur[3 * HU]);
    }
    // h(0) = 0
    for (int idx = tid; idx < HU * 8; idx += 256) hS[idx] = 0.0f;
    __syncthreads();

    float c[NB];
    #pragma unroll
    for (int b = 0; b < NB; b++) c[b] = 0.0f;
    int cur = 0;

    for (int t = 0; t < T; t++) {
        const int tt = dir ? (T - 1 - t) : t;

        // acc initialized with xz (includes input projection + bias)
        float4 acc[NB];
        #pragma unroll
        for (int b = 0; b < NB; b++) {
            const float* xp = xzd + (size_t)(b0 + b) * strideB + (size_t)tt * strideT + j;
            acc[b] = make_float4(xp[0], xp[HU], xp[2 * HU], xp[3 * HU]);
        }

        const float* hrow = hS + cur * (HU * 8);

        // smem-resident U rows
        #pragma unroll 8
        for (int k = 0; k < KSMEM; k++) {
            float4 w = Us4[k * HU + j];
            float hv[NB];
            if constexpr (NB == 4) {
                float4 h4 = *(const float4*)(hrow + k * 8 + bg * 4);
                hv[0] = h4.x; hv[1] = h4.y; hv[2] = h4.z; hv[3] = h4.w;
            } else {
                float2 h2 = *(const float2*)(hrow + k * 8 + bg * 2);
                hv[0] = h2.x; hv[1] = h2.y;
            }
            #pragma unroll
            for (int b = 0; b < NB; b++) {
                acc[b].x += hv[b] * w.x; acc[b].y += hv[b] * w.y;
                acc[b].z += hv[b] * w.z; acc[b].w += hv[b] * w.w;
            }
        }
        // register-resident U rows
        #pragma unroll
        for (int r = 0; r < REGK; r++) {
            const int k = KSMEM + r;
            float4 w = wreg[r];
            float hv[NB];
            if constexpr (NB == 4) {
                float4 h4 = *(const float4*)(hrow + k * 8 + bg * 4);
                hv[0] = h4.x; hv[1] = h4.y; hv[2] = h4.z; hv[3] = h4.w;
            } else {
                float2 h2 = *(const float2*)(hrow + k * 8 + bg * 2);
                hv[0] = h2.x; hv[1] = h2.y;
            }
            #pragma unroll
            for (int b = 0; b < NB; b++) {
                acc[b].x += hv[b] * w.x; acc[b].y += hv[b] * w.y;
                acc[b].z += hv[b] * w.z; acc[b].w += hv[b] * w.w;
            }
        }

        // gates + state update
        float hn[NB];
        #pragma unroll
        for (int b = 0; b < NB; b++) {
            float ig = sigm(acc[b].x);
            float fg = sigm(acc[b].y);
            float gg = fmaxf(acc[b].z, 0.0f);
            float og = sigm(acc[b].w);
            c[b] = fg * c[b] + ig * gg;
            hn[b] = og * fmaxf(c[b], 0.0f);
        }

        if (SEQ) {
            #pragma unroll
            for (int b = 0; b < NB; b++)
                outd[((size_t)(b0 + b) * T + tt) * ldo + j] = hn[b];
        } else if (t == T - 1) {
            #pragma unroll
            for (int b = 0; b < NB; b++)
                outd[(size_t)(b0 + b) * ldo + j] = hn[b];
        }

        // publish h for next step
        float* hw = hS + (cur ^ 1) * (HU * 8) + j * 8 + bg * NB;
        if constexpr (NB == 4)
            *(float4*)hw = make_float4(hn[0], hn[1], hn[2], hn[3]);
        else
            *(float2*)hw = make_float2(hn[0], hn[1]);

        __syncthreads();
        cur ^= 1;
    }
}

// ---------------------------------------------------------------------------
// Launch sequence
// ---------------------------------------------------------------------------
extern "C" void kernel_launch(void* const* d_in, const int* in_sizes, int n_in,
                              void* d_out, int out_size)
{
    const float* x    = (const float*)d_in[0];
    const float* e1fW = (const float*)d_in[1];
    const float* e1fU = (const float*)d_in[2];
    const float* e1fb = (const float*)d_in[3];
    const float* e1bW = (const float*)d_in[4];
    const float* e1bU = (const float*)d_in[5];
    const float* e1bb = (const float*)d_in[6];
    const float* e2fW = (const float*)d_in[7];
    const float* e2fU = (const float*)d_in[8];
    const float* e2fb = (const float*)d_in[9];
    const float* e2bW = (const float*)d_in[10];
    const float* e2bU = (const float*)d_in[11];
    const float* e2bb = (const float*)d_in[12];
    const float* d1fW = (const float*)d_in[13];
    const float* d1fU = (const float*)d_in[14];
    const float* d1fb = (const float*)d_in[15];
    const float* d1bW = (const float*)d_in[16];
    const float* d1bU = (const float*)d_in[17];
    const float* d1bb = (const float*)d_in[18];
    const float* d2fW = (const float*)d_in[19];
    const float* d2fU = (const float*)d_in[20];
    const float* d2fb = (const float*)d_in[21];
    const float* d2bW = (const float*)d_in[22];
    const float* d2bU = (const float*)d_in[23];
    const float* d2bb = (const float*)d_in[24];
    const float* Wd   = (const float*)d_in[25];
    const float* bd   = (const float*)d_in[26];

    float *xz1, *xz2, *h1, *hd1, *z, *xzd1;
    cudaGetSymbolAddress((void**)&xz1,  g_xz1);
    cudaGetSymbolAddress((void**)&xz2,  g_xz2);
    cudaGetSymbolAddress((void**)&h1,   g_h1);
    cudaGetSymbolAddress((void**)&hd1,  g_hd1);
    cudaGetSymbolAddress((void**)&z,    g_z);
    cudaGetSymbolAddress((void**)&xzd1, g_xzd1);

    // smem sizes: HU=128: 104 U rows * 128 * 16B + 2*128*8*4B = 221184
    //             HU=64 :  64 U rows *  64 * 16B + 2* 64*8*4B =  69632
    const int SMEM128 = 104 * 128 * 16 + 2 * 128 * 8 * 4;
    const int SMEM64  =  64 *  64 * 16 + 2 *  64 * 8 * 4;
    cudaFuncSetAttribute(lstm_kernel<128, 104, true>,
                         cudaFuncAttributeMaxDynamicSharedMemorySize, SMEM128);
    cudaFuncSetAttribute(lstm_kernel<64, 64, true>,
                         cudaFuncAttributeMaxDynamicSharedMemorySize, SMEM64);
    cudaFuncSetAttribute(lstm_kernel<64, 64, false>,
                         cudaFuncAttributeMaxDynamicSharedMemorySize, SMEM64);

    const int T = 256;

    // ---- e1: xz = x @ W + b  (both dirs into [BT,1024]) ----
    sgemm_bias<<<dim3(4, 1024), 256>>>(x, e1fW, e1fb, xz1,       BT, 512, 64, 1024);
    sgemm_bias<<<dim3(4, 1024), 256>>>(x, e1bW, e1bb, xz1 + 512, BT, 512, 64, 1024);
    // ---- e1 recurrence: h1 [BT,256] ----
    lstm_kernel<128, 104, true><<<dim3(64, 2), 256, SMEM128>>>(
        xz1, (size_t)T * 1024, 1024, e1fU, e1bU, h1, 256, T);

    // ---- e2: xz = h1 @ W + b  [BT,512] ----
    sgemm_bias<<<dim3(2, 1024), 256>>>(h1, e2fW, e2fb, xz2,       BT, 256, 256, 512);
    sgemm_bias<<<dim3(2, 1024), 256>>>(h1, e2bW, e2bb, xz2 + 256, BT, 256, 256, 512);
    // ---- e2 recurrence, final states only: z [B,128] ----
    lstm_kernel<64, 64, false><<<dim3(64, 2), 256, SMEM64>>>(
        xz2, (size_t)T * 512, 512, e2fU, e2bU, z, 128, T);

    // ---- d1: input is z broadcast over T -> xz computed ONCE per batch row ----
    sgemm_bias<<<dim3(2, 4), 256>>>(z, d1fW, d1fb, xzd1,       512, 256, 128, 512);
    sgemm_bias<<<dim3(2, 4), 256>>>(z, d1bW, d1bb, xzd1 + 256, 512, 256, 128, 512);
    // ---- d1 recurrence (strideT = 0): hd1 [BT,128] ----
    lstm_kernel<64, 64, true><<<dim3(64, 2), 256, SMEM64>>>(
        xzd1, 512, 0, d1fU, d1bU, hd1, 128, T);

    // ---- d2: xz = hd1 @ W + b  (reuse xz1) ----
    sgemm_bias<<<dim3(4, 1024), 256>>>(hd1, d2fW, d2fb, xz1,       BT, 512, 128, 1024);
    sgemm_bias<<<dim3(4, 1024), 256>>>(hd1, d2bW, d2bb, xz1 + 512, BT, 512, 128, 1024);
    // ---- d2 recurrence: hd2 [BT,256] (reuse h1) ----
    lstm_kernel<128, 104, true><<<dim3(64, 2), 256, SMEM128>>>(
        xz1, (size_t)T * 1024, 1024, d2fU, d2bU, h1, 256, T);

    // ---- dense: out = hd2 @ Wd + bd  [BT,64] ----
    sgemm_bias<<<dim3(1, 1024), 256>>>(h1, Wd, bd, (float*)d_out, BT, 64, 256, 64);
}

// round 2
// speedup vs baseline: 1.0305x; 1.0305x over previous
#include <cuda_runtime.h>
#include <math.h>

// B=512, T=256, F=64, N=128
#define BT 131072

typedef unsigned long long u64;

// Scratch (device globals)
__device__ float g_xz1[134217728];   // [BT,1024] e1/d2 xz
__device__ float g_xz2[67108864];    // [BT, 512] e2 xz
__device__ float g_h1 [33554432];    // [BT, 256] e1 / d2 output
__device__ float g_hd1[16777216];    // [BT, 128] d1 output
__device__ float g_z  [65536];       // [B, 128]
__device__ float g_xzd1[262144];     // [B, 512]

__device__ __forceinline__ float sigm(float x) {
    return __fdividef(1.0f, 1.0f + __expf(-x));
}

// ---- packed f32x2 helpers (Blackwell) ----
__device__ __forceinline__ u64 pk2(float x, float y) {
    u64 r; asm("mov.b64 %0, {%1, %2};" : "=l"(r) : "f"(x), "f"(y)); return r;
}
__device__ __forceinline__ u64 dup2(float x) {
    u64 r; asm("mov.b64 %0, {%1, %1};" : "=l"(r) : "f"(x)); return r;
}
__device__ __forceinline__ float2 upk(u64 v) {
    float2 r; asm("mov.b64 {%0, %1}, %2;" : "=f"(r.x), "=f"(r.y) : "l"(v)); return r;
}
__device__ __forceinline__ void fma2(u64 &d, u64 a, u64 b) {
    asm("fma.rn.f32x2 %0, %1, %2, %0;" : "+l"(d) : "l"(a), "l"(b));
}

// ---------------------------------------------------------------------------
// SGEMM + bias, fp32x2 inner product, double-buffered smem.
// C[M,N] = A[M,K] @ W[K,N] + bias[N]. 128x128 tile, BK=8, 256 thr, 8x8/thr.
// M%128==0, K%8==0, N guarded.
// ---------------------------------------------------------------------------
__global__ __launch_bounds__(256) void sgemm_bias(
    const float* __restrict__ A, const float* __restrict__ W,
    const float* __restrict__ bias, float* __restrict__ C,
    int M, int N, int K, int ldc)
{
    __shared__ float As[2][8][128];
    __shared__ float Bs[2][8][128];

    const int tid = threadIdx.x;
    const int bm = blockIdx.y * 128;
    const int bn = blockIdx.x * 128;
    const int m0 = (tid / 16) * 8;
    const int n0 = (tid % 16) * 8;
    const int arow = tid / 2,  acol = (tid % 2) * 4;
    const int brow = tid / 32, bcol = (tid % 32) * 4;

    u64 acc[8][4];
    #pragma unroll
    for (int i = 0; i < 8; i++)
        #pragma unroll
        for (int jp = 0; jp < 4; jp++) acc[i][jp] = 0ull;

    // prologue: tile 0 -> buf 0
    float4 a4 = *(const float4*)(A + (size_t)(bm + arow) * K + acol);
    float4 b4 = make_float4(0.f, 0.f, 0.f, 0.f);
    if (bn + bcol < N) b4 = *(const float4*)(W + (size_t)brow * N + bn + bcol);
    As[0][acol + 0][arow] = a4.x; As[0][acol + 1][arow] = a4.y;
    As[0][acol + 2][arow] = a4.z; As[0][acol + 3][arow] = a4.w;
    *(float4*)&Bs[0][brow][bcol] = b4;
    __syncthreads();

    const int nk = K / 8;
    for (int kt = 0; kt < nk; kt++) {
        const int buf = kt & 1;
        if (kt + 1 < nk) {
            const int k0 = (kt + 1) * 8;
            a4 = *(const float4*)(A + (size_t)(bm + arow) * K + k0 + acol);
            b4 = make_float4(0.f, 0.f, 0.f, 0.f);
            if (bn + bcol < N)
                b4 = *(const float4*)(W + (size_t)(k0 + brow) * N + bn + bcol);
        }
        #pragma unroll
        for (int kk = 0; kk < 8; kk++) {
            float a[8];
            *(float4*)(a)     = *(const float4*)&As[buf][kk][m0];
            *(float4*)(a + 4) = *(const float4*)&As[buf][kk][m0 + 4];
            u64 bb[4];
            const u64* bp = (const u64*)&Bs[buf][kk][n0];
            bb[0] = bp[0]; bb[1] = bp[1]; bb[2] = bp[2]; bb[3] = bp[3];
            #pragma unroll
            for (int i = 0; i < 8; i++) {
                u64 ap = dup2(a[i]);
                fma2(acc[i][0], ap, bb[0]);
                fma2(acc[i][1], ap, bb[1]);
                fma2(acc[i][2], ap, bb[2]);
                fma2(acc[i][3], ap, bb[3]);
            }
        }
        if (kt + 1 < nk) {
            const int nb = buf ^ 1;
            As[nb][acol + 0][arow] = a4.x; As[nb][acol + 1][arow] = a4.y;
            As[nb][acol + 2][arow] = a4.z; As[nb][acol + 3][arow] = a4.w;
            *(float4*)&Bs[nb][brow][bcol] = b4;
        }
        __syncthreads();
    }

    #pragma unroll
    for (int i = 0; i < 8; i++) {
        size_t row = (size_t)(bm + m0 + i) * ldc;
        #pragma unroll
        for (int jp = 0; jp < 4; jp++) {
            float2 v = upk(acc[i][jp]);
            int n = bn + n0 + jp * 2;
            if (n < N)     C[row + n]     = v.x + bias[n];
            if (n + 1 < N) C[row + n + 1] = v.y + bias[n + 1];
        }
    }
}

// ---------------------------------------------------------------------------
// LSTM recurrence. 128 threads/CTA, grid (64 batch-chunks, 2 dirs).
// Each thread owns column j and NB=HU/16 batch rows (8 rows per CTA).
// U gate-pair-packed: ulonglong2 per (k,j) = ((Ui,Uf),(Ug,Uo)).
// KSMEM rows of U in smem, REGK rows in registers.
// h stored duplicated (h,h) as float2 in smem -> direct u64 FFMA2 operand,
// broadcast LDS. xz prefetched one step ahead.
// ---------------------------------------------------------------------------
template<int HU, int KSMEM, bool SEQ>
__global__ __launch_bounds__(128, 1)
void lstm_kernel(const float* __restrict__ xz, size_t strideB, size_t strideT,
                 const float* __restrict__ Uf, const float* __restrict__ Ub,
                 float* __restrict__ out, int ldo, int T)
{
    constexpr int NB   = HU / 16;       // 8 for HU=128, 4 for HU=64
    constexpr int REGK = HU - KSMEM;

    extern __shared__ char smraw[];
    ulonglong2* Us = (ulonglong2*)smraw;                      // [KSMEM*HU]
    float2*     hS = (float2*)(smraw + (size_t)KSMEM * HU * 16); // [2][HU*8]

    const int tid = threadIdx.x;
    const int j   = tid % HU;
    const int bg  = tid / HU;           // 0 for HU=128; 0..1 for HU=64
    const int dir = blockIdx.y;
    const int b0  = blockIdx.x * 8 + bg * NB;

    const float* U    = dir ? Ub : Uf;
    const float* xzd  = xz + (size_t)dir * (4 * HU);
    float*       outd = out + dir * HU;

    for (int idx = tid; idx < KSMEM * HU; idx += 128) {
        int k = idx / HU, jj = idx % HU;
        const float* ur = U + (size_t)k * (4 * HU) + jj;
        Us[idx] = make_ulonglong2(pk2(ur[0], ur[HU]), pk2(ur[2 * HU], ur[3 * HU]));
    }
    ulonglong2 wreg[REGK > 0 ? REGK : 1];
    #pragma unroll
    for (int r = 0; r < REGK; r++) {
        const float* ur = U + (size_t)(KSMEM + r) * (4 * HU) + j;
        wreg[r] = make_ulonglong2(pk2(ur[0], ur[HU]), pk2(ur[2 * HU], ur[3 * HU]));
    }
    for (int idx = tid; idx < HU * 8; idx += 128) hS[idx] = make_float2(0.f, 0.f);
    __syncthreads();

    float c[NB];
    #pragma unroll
    for (int b = 0; b < NB; b++) c[b] = 0.f;
    int cur = 0;

    // prefetch xz for t=0
    float xn[NB][4];
    {
        const int tt = dir ? (T - 1) : 0;
        #pragma unroll
        for (int b = 0; b < NB; b++) {
            const float* xp = xzd + (size_t)(b0 + b) * strideB + (size_t)tt * strideT + j;
            xn[b][0] = xp[0]; xn[b][1] = xp[HU];
            xn[b][2] = xp[2 * HU]; xn[b][3] = xp[3 * HU];
        }
    }

    for (int t = 0; t < T; t++) {
        const int tt = dir ? (T - 1 - t) : t;

        u64 aif[NB], ago[NB];
        #pragma unroll
        for (int b = 0; b < NB; b++) {
            aif[b] = pk2(xn[b][0], xn[b][1]);
            ago[b] = pk2(xn[b][2], xn[b][3]);
        }
        if (t + 1 < T) {  // prefetch next step early; overlaps k-loop
            const int tn = dir ? (T - 2 - t) : (t + 1);
            #pragma unroll
            for (int b = 0; b < NB; b++) {
                const float* xp = xzd + (size_t)(b0 + b) * strideB + (size_t)tn * strideT + j;
                xn[b][0] = xp[0]; xn[b][1] = xp[HU];
                xn[b][2] = xp[2 * HU]; xn[b][3] = xp[3 * HU];
            }
        }

        const float2* hrow = hS + cur * (HU * 8);

        #pragma unroll 4
        for (int k = 0; k < KSMEM; k++) {
            ulonglong2 w = Us[k * HU + j];
            const ulonglong2* hp = (const ulonglong2*)(hrow + k * 8 + bg * NB);
            #pragma unroll
            for (int q = 0; q < NB / 2; q++) {
                ulonglong2 h2 = hp[q];
                fma2(aif[2 * q],     h2.x, w.x);
                fma2(ago[2 * q],     h2.x, w.y);
                fma2(aif[2 * q + 1], h2.y, w.x);
                fma2(ago[2 * q + 1], h2.y, w.y);
            }
        }
        #pragma unroll
        for (int r = 0; r < REGK; r++) {
            const int k = KSMEM + r;
            ulonglong2 w = wreg[r];
            const ulonglong2* hp = (const ulonglong2*)(hrow + k * 8 + bg * NB);
            #pragma unroll
            for (int q = 0; q < NB / 2; q++) {
                ulonglong2 h2 = hp[q];
                fma2(aif[2 * q],     h2.x, w.x);
                fma2(ago[2 * q],     h2.x, w.y);
                fma2(aif[2 * q + 1], h2.y, w.x);
                fma2(ago[2 * q + 1], h2.y, w.y);
            }
        }

        float hn[NB];
        #pragma unroll
        for (int b = 0; b < NB; b++) {
            float2 vif = upk(aif[b]);
            float2 vgo = upk(ago[b]);
            float ig = sigm(vif.x);
            float fg = sigm(vif.y);
            float gg = fmaxf(vgo.x, 0.f);
            float og = sigm(vgo.y);
            c[b] = fg * c[b] + ig * gg;
            hn[b] = og * fmaxf(c[b], 0.f);
        }

        if (SEQ) {
            #pragma unroll
            for (int b = 0; b < NB; b++)
                outd[((size_t)(b0 + b) * T + tt) * ldo + j] = hn[b];
        } else if (t == T - 1) {
            #pragma unroll
            for (int b = 0; b < NB; b++)
                outd[(size_t)(b0 + b) * ldo + j] = hn[b];
        }

        // publish duplicated h for next step
        float2* hw = hS + (cur ^ 1) * (HU * 8) + j * 8 + bg * NB;
        #pragma unroll
        for (int q = 0; q < NB / 2; q++)
            *(float4*)(hw + 2 * q) =
                make_float4(hn[2 * q], hn[2 * q], hn[2 * q + 1], hn[2 * q + 1]);

        __syncthreads();
        cur ^= 1;
    }
}

// ---------------------------------------------------------------------------
extern "C" void kernel_launch(void* const* d_in, const int* in_sizes, int n_in,
                              void* d_out, int out_size)
{
    const float* x    = (const float*)d_in[0];
    const float* e1fW = (const float*)d_in[1];
    const float* e1fU = (const float*)d_in[2];
    const float* e1fb = (const float*)d_in[3];
    const float* e1bW = (const float*)d_in[4];
    const float* e1bU = (const float*)d_in[5];
    const float* e1bb = (const float*)d_in[6];
    const float* e2fW = (const float*)d_in[7];
    const float* e2fU = (const float*)d_in[8];
    const float* e2fb = (const float*)d_in[9];
    const float* e2bW = (const float*)d_in[10];
    const float* e2bU = (const float*)d_in[11];
    const float* e2bb = (const float*)d_in[12];
    const float* d1fW = (const float*)d_in[13];
    const float* d1fU = (const float*)d_in[14];
    const float* d1fb = (const float*)d_in[15];
    const float* d1bW = (const float*)d_in[16];
    const float* d1bU = (const float*)d_in[17];
    const float* d1bb = (const float*)d_in[18];
    const float* d2fW = (const float*)d_in[19];
    const float* d2fU = (const float*)d_in[20];
    const float* d2fb = (const float*)d_in[21];
    const float* d2bW = (const float*)d_in[22];
    const float* d2bU = (const float*)d_in[23];
    const float* d2bb = (const float*)d_in[24];
    const float* Wd   = (const float*)d_in[25];
    const float* bd   = (const float*)d_in[26];

    float *xz1, *xz2, *h1, *hd1, *z, *xzd1;
    cudaGetSymbolAddress((void**)&xz1,  g_xz1);
    cudaGetSymbolAddress((void**)&xz2,  g_xz2);
    cudaGetSymbolAddress((void**)&h1,   g_h1);
    cudaGetSymbolAddress((void**)&hd1,  g_hd1);
    cudaGetSymbolAddress((void**)&z,    g_z);
    cudaGetSymbolAddress((void**)&xzd1, g_xzd1);

    // smem: HU=128/KSMEM=100: 100*128*16 + 2*128*8*8 = 221184
    //       HU=64 /KSMEM=48 :  48*64*16  + 2*64*8*8  =  57344
    const int SMEM128 = 100 * 128 * 16 + 2 * 128 * 8 * 8;
    const int SMEM64  =  48 *  64 * 16 + 2 *  64 * 8 * 8;
    cudaFuncSetAttribute(lstm_kernel<128, 100, true>,
                         cudaFuncAttributeMaxDynamicSharedMemorySize, SMEM128);
    cudaFuncSetAttribute(lstm_kernel<64, 48, true>,
                         cudaFuncAttributeMaxDynamicSharedMemorySize, SMEM64);
    cudaFuncSetAttribute(lstm_kernel<64, 48, false>,
                         cudaFuncAttributeMaxDynamicSharedMemorySize, SMEM64);

    const int T = 256;

    // e1: xz = x @ W + b
    sgemm_bias<<<dim3(4, 1024), 256>>>(x, e1fW, e1fb, xz1,       BT, 512, 64, 1024);
    sgemm_bias<<<dim3(4, 1024), 256>>>(x, e1bW, e1bb, xz1 + 512, BT, 512, 64, 1024);
    lstm_kernel<128, 100, true><<<dim3(64, 2), 128, SMEM128>>>(
        xz1, (size_t)T * 1024, 1024, e1fU, e1bU, h1, 256, T);

    // e2
    sgemm_bias<<<dim3(2, 1024), 256>>>(h1, e2fW, e2fb, xz2,       BT, 256, 256, 512);
    sgemm_bias<<<dim3(2, 1024), 256>>>(h1, e2bW, e2bb, xz2 + 256, BT, 256, 256, 512);
    lstm_kernel<64, 48, false><<<dim3(64, 2), 128, SMEM64>>>(
        xz2, (size_t)T * 512, 512, e2fU, e2bU, z, 128, T);

    // d1: z broadcast over T -> xz computed once per batch row
    sgemm_bias<<<dim3(2, 4), 256>>>(z, d1fW, d1fb, xzd1,       512, 256, 128, 512);
    sgemm_bias<<<dim3(2, 4), 256>>>(z, d1bW, d1bb, xzd1 + 256, 512, 256, 128, 512);
    lstm_kernel<64, 48, true><<<dim3(64, 2), 128, SMEM64>>>(
        xzd1, 512, 0, d1fU, d1bU, hd1, 128, T);

    // d2
    sgemm_bias<<<dim3(4, 1024), 256>>>(hd1, d2fW, d2fb, xz1,       BT, 512, 128, 1024);
    sgemm_bias<<<dim3(4, 1024), 256>>>(hd1, d2bW, d2bb, xz1 + 512, BT, 512, 128, 1024);
    lstm_kernel<128, 100, true><<<dim3(64, 2), 128, SMEM128>>>(
        xz1, (size_t)T * 1024, 1024, d2fU, d2bU, h1, 256, T);

    // dense
    sgemm_bias<<<dim3(1, 1024), 256>>>(h1, Wd, bd, (float*)d_out, BT, 64, 256, 64);
}